// round 2
// baseline (speedup 1.0000x reference)
#include <cuda_runtime.h>
#include <math.h>

#define BATCH   16384
#define TSTEPS  300
#define NBASIS  32
#define HID     64
#define DTC     (1.0f/300.0f)
#define BPB     128              // batches per block
#define THREADS 256              // 2 channels per batch -> 256 channels per block
#define NBLOCKS (BATCH/BPB)      // 128

#define OFF_SIG ((size_t)BATCH*2*TSTEPS)                 // a region size
#define OFF_VAL (OFF_SIG + (size_t)BATCH*2)              // + sigma region

// ---- dynamic shared memory layout (in floats) ----
#define SH_P     0                   // 9600  : p[k][j] = psi*x/sum(psi)
#define SH_HT    (SH_P + 9600)       // 8192  : hidden transposed [64][128]
#define SH_W2    (SH_HT + 8192)      // 4224  : fc2m_w [66][64]
#define SH_B2    (SH_W2 + 4224)      // 68
#define SH_F1W   (SH_B2 + 68)        // 192
#define SH_F1B   (SH_F1W + 192)      // 64
#define SH_SW    (SH_F1B + 64)       // 128
#define SH_VW    (SH_SW + 128)       // 128
#define SH_SB    (SH_VW + 128)       // 4
#define SH_VB    (SH_SB + 4)         // 4
#define SH_C     (SH_VB + 4)         // 32
#define SH_S2    (SH_C + 32)         // 32
#define SH_V     (SH_S2 + 32)        // 256   : value head per channel
#define SH_TR    (SH_V + 256)        // 7936  : 8 warps x [32][31] transpose buf
#define SH_TOTAL (SH_TR + 7936)      // 30860 floats = 123440 bytes

extern "C" __global__ void __launch_bounds__(THREADS, 1)
ndp_kernel(const float* __restrict__ state,
           const float* __restrict__ fc1w, const float* __restrict__ fc1b,
           const float* __restrict__ w2,   const float* __restrict__ b2,
           const float* __restrict__ sw,   const float* __restrict__ sb,
           const float* __restrict__ vw,   const float* __restrict__ vb,
           const float* __restrict__ dc,   const float* __restrict__ ds2,
           float* __restrict__ out)
{
    extern __shared__ float sm[];
    const int tid  = threadIdx.x;
    const int bk   = blockIdx.x;
    const int lane = tid & 31;
    const int warp = tid >> 5;

    // ---- stage weights / params into shared ----
    for (int i = tid; i < 66*64; i += THREADS) sm[SH_W2 + i] = w2[i];
    for (int i = tid; i < 66;   i += THREADS) sm[SH_B2 + i] = b2[i];
    for (int i = tid; i < 192;  i += THREADS) sm[SH_F1W + i] = fc1w[i];
    for (int i = tid; i < 64;   i += THREADS) sm[SH_F1B + i] = fc1b[i];
    for (int i = tid; i < 128;  i += THREADS) sm[SH_SW + i] = sw[i];
    for (int i = tid; i < 128;  i += THREADS) sm[SH_VW + i] = vw[i];
    for (int i = tid; i < 2;    i += THREADS) { sm[SH_SB + i] = sb[i]; sm[SH_VB + i] = vb[i]; }
    for (int i = tid; i < 32;   i += THREADS) { sm[SH_C + i] = dc[i]; sm[SH_S2 + i] = ds2[i]; }
    __syncthreads();

    // ---- phase / normalized-psi table: p[k][j] = psi_kj * x_k / sum_j psi_kj ----
    // x_k = (1-DT)^(k+1). Each warp iteration covers exactly one k-row (lane = j),
    // warp-shuffle reduction for the row sum; stores are lane-consecutive (no conflicts).
    {
        const float l2 = log2f(1.0f - DTC);
        for (int base = 0; base < TSTEPS*NBASIS; base += THREADS) {
            int idx = base + tid;   // 9600 divisible by 256 -> guard always uniform
            if (idx < TSTEPS*NBASIS) {
                int k = idx >> 5, j = idx & 31;
                float x  = exp2f((float)(k + 1) * l2);
                float dd = x - sm[SH_C + j];
                float psi = expf(-0.5f * dd * dd / sm[SH_S2 + j]);
                float s = psi;
                #pragma unroll
                for (int o = 16; o; o >>= 1) s += __shfl_xor_sync(0xffffffffu, s, o);
                sm[SH_P + idx] = psi * (x / s);
            }
        }
    }

    // ---- fc1 hidden layer, stored transposed [64][128] (lane-consecutive writes) ----
    {
        int bb = tid & (BPB - 1);
        int gb = bk*BPB + bb;
        float s0 = state[gb*3+0], s1 = state[gb*3+1], s2v = state[gb*3+2];
        for (int hh = (tid >> 7); hh < HID; hh += 2) {
            float t = sm[SH_F1W + hh*3+0]*s0 + sm[SH_F1W + hh*3+1]*s1
                    + sm[SH_F1W + hh*3+2]*s2v + sm[SH_F1B + hh];
            sm[SH_HT + hh*BPB + bb] = tanhf(t) * 0.1f;
        }
    }
    __syncthreads();

    // ---- per-channel GEMV: goal, 32 basis weights, a_z, sigma-pre, value-pre ----
    const int b  = tid >> 1;
    const int d  = tid & 1;
    const int gb = bk*BPB + b;

    float wv[32];
    #pragma unroll
    for (int j = 0; j < 32; j++) wv[j] = sm[SH_B2 + 2 + d*32 + j];
    float goal = sm[SH_B2 + d];
    float azv  = sm[SH_B2 + 65];
    float sgp  = sm[SH_SB + d];
    float vlp  = sm[SH_VB + d];

    const float* w2r = sm + SH_W2;
    #pragma unroll
    for (int k = 0; k < HID; k += 4) {
        float h0 = sm[SH_HT + (k+0)*BPB + b];
        float h1 = sm[SH_HT + (k+1)*BPB + b];
        float h2 = sm[SH_HT + (k+2)*BPB + b];
        float h3 = sm[SH_HT + (k+3)*BPB + b];
        float4 g4 = *(const float4*)(w2r + d*HID + k);
        goal += h0*g4.x + h1*g4.y + h2*g4.z + h3*g4.w;
        float4 a4 = *(const float4*)(w2r + 65*HID + k);
        azv  += h0*a4.x + h1*a4.y + h2*a4.z + h3*a4.w;
        float4 s4 = *(const float4*)(sm + SH_SW + d*HID + k);
        sgp  += h0*s4.x + h1*s4.y + h2*s4.z + h3*s4.w;
        float4 v4 = *(const float4*)(sm + SH_VW + d*HID + k);
        vlp  += h0*v4.x + h1*v4.y + h2*v4.z + h3*v4.w;
        #pragma unroll
        for (int j = 0; j < 32; j++) {
            float4 ww = *(const float4*)(w2r + (2 + d*32 + j)*HID + k);
            wv[j] += h0*ww.x + h1*ww.y + h2*ww.z + h3*ww.w;
        }
    }

    azv = fminf(fmaxf(azv, 0.5f), 30.0f);
    // sigma = sigmoid(pre)*1.0 + 0.001 ; flat layout [B*2]
    out[OFF_SIG + (size_t)(bk*THREADS) + tid] = 1.0f / (1.0f + expf(-sgp)) + 0.001f;
    sm[SH_V + tid] = vlp;

    // ---- DMP Euler rollout ----
    const float y0 = state[gb*3 + d];
    const float G  = goal - y0;
    const float bz = azv * 0.25f;
    float y = y0, z = 0.01f;          // z0 = dy0 * tau = 0.01

    float* trb   = sm + SH_TR + warp*(32*31);
    float* out_a = out + (size_t)(bk*THREADS)*TSTEPS;
    const float4* p4base = (const float4*)(sm + SH_P);

    for (int ch = 0; ch < 10; ch++) {             // 10 chunks x 30 steps
        #pragma unroll 3
        for (int s = 0; s < 30; s++) {
            int k = ch*30 + s;
            const float4* p4 = p4base + k*8;
            float a0 = 0.f, a1 = 0.f, a2 = 0.f, a3 = 0.f;
            #pragma unroll
            for (int q = 0; q < 8; q++) {
                float4 pv = p4[q];                // warp-broadcast LDS.128
                a0 += wv[q*4+0]*pv.x;
                a1 += wv[q*4+1]*pv.y;
                a2 += wv[q*4+2]*pv.z;
                a3 += wv[q*4+3]*pv.w;
            }
            float fx = ((a0+a1)+(a2+a3)) * G;
            float dz = azv * (bz*(goal - y) - z) + fx;
            // Reproduce reference quantization: a[t] = fl(y + fl(z*DT)) - y (Sterbenz-exact)
            float inc  = __fmul_rn(z, DTC);
            float ynew = __fadd_rn(y, inc);
            trb[lane*31 + s] = ynew - y;
            y = ynew;
            z = __fadd_rn(z, __fmul_rn(dz, DTC));
        }
        __syncwarp();
        // transposed, coalesced store of this warp's 32 channels x 30 steps
        int t0 = ch*30;
        #pragma unroll
        for (int i = 0; i < 32; i++) {
            if (lane < 30)
                out_a[(size_t)(warp*32 + i)*TSTEPS + t0 + lane] = trb[i*31 + lane];
        }
        __syncwarp();
    }

    // ---- value broadcast fill: [B,2,300], v constant over t, coalesced ----
    __syncthreads();
    float* out_v = out + OFF_VAL + (size_t)(bk*THREADS)*TSTEPS;
    for (int ch = 0; ch < THREADS; ch++) {
        float vvv = sm[SH_V + ch];
        for (int t = tid; t < TSTEPS; t += THREADS)
            out_v[(size_t)ch*TSTEPS + t] = vvv;
    }
}

extern "C" void kernel_launch(void* const* d_in, const int* in_sizes, int n_in,
                              void* d_out, int out_size)
{
    (void)in_sizes; (void)n_in; (void)out_size;
    cudaFuncSetAttribute(ndp_kernel, cudaFuncAttributeMaxDynamicSharedMemorySize,
                         SH_TOTAL * (int)sizeof(float));
    ndp_kernel<<<NBLOCKS, THREADS, SH_TOTAL * sizeof(float)>>>(
        (const float*)d_in[0],  (const float*)d_in[1], (const float*)d_in[2],
        (const float*)d_in[3],  (const float*)d_in[4], (const float*)d_in[5],
        (const float*)d_in[6],  (const float*)d_in[7], (const float*)d_in[8],
        (const float*)d_in[9],  (const float*)d_in[10], (float*)d_out);
}

// round 3
// speedup vs baseline: 2.2500x; 2.2500x over previous
#include <cuda_runtime.h>
#include <math.h>

#define BATCH   16384
#define TSTEPS  300
#define NBASIS  32
#define HID     64
#define DTC     (1.0f/300.0f)
#define BPB     64               // batches per block
#define THREADS 128              // 1 thread = 1 channel (batch, dim)
#define NBLOCKS (BATCH/BPB)      // 256

#define OFF_SIG ((size_t)BATCH*2*TSTEPS)
#define OFF_VAL (OFF_SIG + (size_t)BATCH*2)

// ---- device-global precomputed tables (written by setup_kernel each call) ----
__device__ float g_r[TSTEPS];        // x_k / sum_j psi_j(x_k)
__device__ float g_Q[2*5*HID];       // poly-coeff map: hidden -> quartic coeffs
__device__ float g_C[10];            // bias part of quartic coeffs, [d*5+m]

// ---- shared memory layout (floats) ----
#define SH_R     0                    // 304  (300 + pad)
#define SH_HT    (SH_R + 304)         // 4096 : hidden transposed [64][64]
#define SH_WD    (SH_HT + 4096)       // 192  : w2 rows 0,1,65
#define SH_SW    (SH_WD + 192)        // 128
#define SH_VW    (SH_SW + 128)        // 128
#define SH_Q     (SH_VW + 128)        // 640
#define SH_B     (SH_Q + 640)         // 20 : b2[0],b2[1],b2[65],sb0,sb1,vb0,vb1,gC[10]
#define SH_F1W   (SH_B + 20)          // 192
#define SH_F1B   (SH_F1W + 192)       // 64
#define SH_V     (SH_F1B + 64)        // 128 : value per channel
#define SH_TR    (SH_V + 128)         // 3968 : 4 warps x [32][31]
#define SH_TOTAL (SH_TR + 3968)       // 9860 floats = 39440 bytes

// ============================================================================
// Setup: channel-independent tables. psi_j(x)=exp(-0.5(x-c_j)^2/s2_j); with
// exponents <= 1.1e-3, 2nd-order Taylor gives sum_j w_j psi_j(x) as a quartic
// in x with coefficients P[m][j]^T w (truncation ~2e-10 relative).
// ============================================================================
__global__ void setup_kernel(const float* __restrict__ w2,
                             const float* __restrict__ b2,
                             const float* __restrict__ dc,
                             const float* __restrict__ ds2)
{
    __shared__ float P[5][NBASIS];
    int t = threadIdx.x;
    if (t < NBASIS) {
        float c = dc[t], s2 = ds2[t];
        float a  = 0.5f / s2;
        float a2 = a * a;
        float c2 = c * c;
        P[0][t] = 1.0f - a*c2 + 0.5f*a2*c2*c2;
        P[1][t] = 2.0f*a*c - 2.0f*a2*c2*c;
        P[2][t] = -a + 3.0f*a2*c2;
        P[3][t] = -2.0f*a2*c;
        P[4][t] = 0.5f*a2;
    }
    __syncthreads();

    if (t < TSTEPS) {   // r table: exact psi sum at x_k = (1-DT)^(k+1)
        float x = exp2f((float)(t + 1) * log2f(1.0f - DTC));
        float S = 0.0f;
        for (int j = 0; j < NBASIS; j++) {
            float dd = x - dc[j];
            S += expf(-0.5f * dd * dd / ds2[j]);
        }
        g_r[t] = x / S;
    }
    // Q[d][m][k] = sum_j w2[(2+32d+j)*64 + k] * P[m][j]
    for (int o = t; o < 2*5*HID; o += blockDim.x) {
        int k = o & 63;
        int m = (o >> 6) % 5;
        int d = o / (5*HID);
        float acc = 0.0f;
        for (int j = 0; j < NBASIS; j++)
            acc += w2[(2 + d*32 + j)*HID + k] * P[m][j];
        g_Q[o] = acc;
    }
    if (t < 10) {
        int d = t / 5, m = t % 5;
        float acc = 0.0f;
        for (int j = 0; j < NBASIS; j++)
            acc += b2[2 + d*32 + j] * P[m][j];
        g_C[t] = acc;
    }
}

// ============================================================================
// Main kernel
// ============================================================================
extern "C" __global__ void __launch_bounds__(THREADS)
ndp_kernel(const float* __restrict__ state,
           const float* __restrict__ fc1w, const float* __restrict__ fc1b,
           const float* __restrict__ w2,   const float* __restrict__ b2,
           const float* __restrict__ sw,   const float* __restrict__ sb,
           const float* __restrict__ vw,   const float* __restrict__ vb,
           float* __restrict__ out)
{
    extern __shared__ float sm[];
    const int tid  = threadIdx.x;
    const int bk   = blockIdx.x;
    const int lane = tid & 31;
    const int warp = tid >> 5;

    // ---- stage tables + weights ----
    for (int i = tid; i < TSTEPS;  i += THREADS) sm[SH_R + i]  = g_r[i];
    for (int i = tid; i < 640;     i += THREADS) sm[SH_Q + i]  = g_Q[i];
    for (int i = tid; i < 128;     i += THREADS) sm[SH_WD + i] = w2[i];         // rows 0,1
    for (int i = tid; i < 64;      i += THREADS) sm[SH_WD + 128 + i] = w2[65*HID + i]; // row 65
    for (int i = tid; i < 128;     i += THREADS) { sm[SH_SW + i] = sw[i]; sm[SH_VW + i] = vw[i]; }
    for (int i = tid; i < 192;     i += THREADS) sm[SH_F1W + i] = fc1w[i];
    for (int i = tid; i < 64;      i += THREADS) sm[SH_F1B + i] = fc1b[i];
    if (tid < 10) sm[SH_B + 7 + tid] = g_C[tid];
    if (tid == 0) {
        sm[SH_B + 0] = b2[0]; sm[SH_B + 1] = b2[1]; sm[SH_B + 2] = b2[65];
        sm[SH_B + 3] = sb[0]; sm[SH_B + 4] = sb[1];
        sm[SH_B + 5] = vb[0]; sm[SH_B + 6] = vb[1];
    }
    __syncthreads();

    // ---- fc1 hidden layer, transposed [64 hid][64 batch] ----
    {
        int bb = tid & 63;
        int gb = bk*BPB + bb;
        float s0 = state[gb*3+0], s1 = state[gb*3+1], s2v = state[gb*3+2];
        for (int hh = (tid >> 6); hh < HID; hh += 2) {
            float v = sm[SH_F1W + hh*3+0]*s0 + sm[SH_F1W + hh*3+1]*s1
                    + sm[SH_F1W + hh*3+2]*s2v + sm[SH_F1B + hh];
            sm[SH_HT + hh*64 + bb] = tanhf(v) * 0.1f;
        }
    }
    __syncthreads();

    // ---- per-channel GEMV: goal, a_z, sigma-pre, value-pre, quartic coeffs ----
    const int b  = tid >> 1;
    const int d  = tid & 1;
    const int gb = bk*BPB + b;

    float goal = sm[SH_B + d];
    float azv  = sm[SH_B + 2];
    float sgp  = sm[SH_B + 3 + d];
    float vlp  = sm[SH_B + 5 + d];
    float c0 = sm[SH_B + 7 + d*5 + 0], c1 = sm[SH_B + 7 + d*5 + 1];
    float c2 = sm[SH_B + 7 + d*5 + 2], c3 = sm[SH_B + 7 + d*5 + 3];
    float c4 = sm[SH_B + 7 + d*5 + 4];

    #pragma unroll
    for (int k = 0; k < HID; k += 4) {
        float h0 = sm[SH_HT + (k+0)*64 + b];
        float h1 = sm[SH_HT + (k+1)*64 + b];
        float h2 = sm[SH_HT + (k+2)*64 + b];
        float h3 = sm[SH_HT + (k+3)*64 + b];
        float4 wg = *(const float4*)(sm + SH_WD + d*64 + k);
        goal += h0*wg.x + h1*wg.y + h2*wg.z + h3*wg.w;
        float4 wa = *(const float4*)(sm + SH_WD + 128 + k);
        azv  += h0*wa.x + h1*wa.y + h2*wa.z + h3*wa.w;
        float4 ws = *(const float4*)(sm + SH_SW + d*64 + k);
        sgp  += h0*ws.x + h1*ws.y + h2*ws.z + h3*ws.w;
        float4 wvv = *(const float4*)(sm + SH_VW + d*64 + k);
        vlp  += h0*wvv.x + h1*wvv.y + h2*wvv.z + h3*wvv.w;
        float4 q;
        q = *(const float4*)(sm + SH_Q + (d*5+0)*64 + k);
        c0 += h0*q.x + h1*q.y + h2*q.z + h3*q.w;
        q = *(const float4*)(sm + SH_Q + (d*5+1)*64 + k);
        c1 += h0*q.x + h1*q.y + h2*q.z + h3*q.w;
        q = *(const float4*)(sm + SH_Q + (d*5+2)*64 + k);
        c2 += h0*q.x + h1*q.y + h2*q.z + h3*q.w;
        q = *(const float4*)(sm + SH_Q + (d*5+3)*64 + k);
        c3 += h0*q.x + h1*q.y + h2*q.z + h3*q.w;
        q = *(const float4*)(sm + SH_Q + (d*5+4)*64 + k);
        c4 += h0*q.x + h1*q.y + h2*q.z + h3*q.w;
    }

    azv = fminf(fmaxf(azv, 0.5f), 30.0f);
    out[OFF_SIG + (size_t)bk*THREADS + tid] = 1.0f / (1.0f + expf(-sgp)) + 0.001f;
    sm[SH_V + tid] = vlp;

    const float y0 = state[gb*3 + d];
    const float G  = goal - y0;
    c0 *= G; c1 *= G; c2 *= G; c3 *= G; c4 *= G;   // fold (goal - y0) into poly
    const float bz = azv * 0.25f;

    // ---- DMP Euler rollout: fx = poly4(x) * r_k ----
    float x = 1.0f, y = y0, z = 0.01f;
    float* trb   = sm + SH_TR + warp*(32*31);
    float* out_a = out + (size_t)bk*THREADS*TSTEPS;

    for (int ch = 0; ch < 10; ch++) {
        #pragma unroll 5
        for (int s = 0; s < 30; s++) {
            int k = ch*30 + s;
            x = __fadd_rn(x, __fmul_rn(-x, DTC));          // matches reference exactly
            float r  = sm[SH_R + k];                        // warp-broadcast LDS
            float f  = __fmaf_rn(__fmaf_rn(__fmaf_rn(__fmaf_rn(c4, x, c3), x, c2), x, c1), x, c0);
            float fx = f * r;
            float dz = __fmaf_rn(azv, __fmaf_rn(bz, goal - y, -z), fx);
            float inc  = __fmul_rn(z, DTC);
            float ynew = __fadd_rn(y, inc);
            trb[lane*31 + s] = ynew - y;                    // Sterbenz-exact a[t]
            y = ynew;
            z = __fadd_rn(z, __fmul_rn(dz, DTC));
        }
        __syncwarp();
        int t0 = ch*30;
        #pragma unroll
        for (int i = 0; i < 32; i++) {
            if (lane < 30)
                out_a[(size_t)(warp*32 + i)*TSTEPS + t0 + lane] = trb[i*31 + lane];
        }
        __syncwarp();
    }

    // ---- value broadcast fill [128 ch][300], float4 stores ----
    __syncthreads();
    float* out_v = out + OFF_VAL + (size_t)bk*THREADS*TSTEPS;
    for (int i = tid; i < THREADS*(TSTEPS/4); i += THREADS) {
        int ch = i / (TSTEPS/4);
        int q  = i - ch*(TSTEPS/4);
        float v = sm[SH_V + ch];
        float4 vv = make_float4(v, v, v, v);
        *(float4*)(out_v + (size_t)ch*TSTEPS + q*4) = vv;
    }
}

extern "C" void kernel_launch(void* const* d_in, const int* in_sizes, int n_in,
                              void* d_out, int out_size)
{
    (void)in_sizes; (void)n_in; (void)out_size;
    setup_kernel<<<1, 320>>>((const float*)d_in[3], (const float*)d_in[4],
                             (const float*)d_in[9], (const float*)d_in[10]);
    ndp_kernel<<<NBLOCKS, THREADS, SH_TOTAL * sizeof(float)>>>(
        (const float*)d_in[0],  (const float*)d_in[1], (const float*)d_in[2],
        (const float*)d_in[3],  (const float*)d_in[4], (const float*)d_in[5],
        (const float*)d_in[6],  (const float*)d_in[7], (const float*)d_in[8],
        (float*)d_out);
}